// round 1
// baseline (speedup 1.0000x reference)
#include <cuda_runtime.h>

// ---------------------------------------------------------------------------
// BVP Helmholtz residual via forward-mode 2nd-order jet propagation.
//
// Channels per sample (C=5): [value, t_x, t_y, t_z, q] where
//   t_d  = d(h)/d(x_d)           (first-order tangent, post-activation)
//   q    = cx*h_xx + cy*h_yy + cz*h_zz   (combined weighted 2nd derivative)
// Linear layer:  u = W v (+b on value only), u_td = W t_d, u_q = W q
// tanh jet:      y = tanh(u), s = 1-y^2
//                t_d <- s*u_td
//                q   <- s*u_q - 2*y*s*(cx*u_tx^2 + cy*u_ty^2 + cz*u_tz^2)
// Residual:      re = AC*q0 + K2*(AC*p0 + A0),  im = BC*q1 + K2*(BC*p1 + B0)
//                K2 = (XC*YC*ZC*k)^2, k = 2*pi*(f*FC+F0)/C0
// ---------------------------------------------------------------------------

#define HD 256
#define BSAMP 16          // samples per block
#define S_STRIDE 80       // 16 samples * 5 channels
#define W_STRIDE 260      // padded (keeps 16B alignment, conflict-free reads)

// smem layout (floats)
#define S_OFF    0
#define W_OFF    (HD * S_STRIDE)            // 20480
#define XYZF_OFF (W_OFF + 32 * W_STRIDE)    // 28800
#define RED_OFF  (XYZF_OFF + 64)            // 28864
#define TOT_OFF  (RED_OFF + 1024)           // 29888
#define SMEM_FLOATS (TOT_OFF + 64)          // 29952 floats = 119808 B

__device__ __forceinline__ unsigned long long pack2(float v) {
    unsigned long long r;
    asm("mov.b64 %0, {%1, %1};" : "=l"(r) : "f"(v));
    return r;
}
__device__ __forceinline__ void fma2(unsigned long long& d,
                                     unsigned long long a,
                                     unsigned long long b) {
    asm("fma.rn.f32x2 %0, %1, %2, %0;" : "+l"(d) : "l"(a), "l"(b));
}
__device__ __forceinline__ float2 unpack2(unsigned long long v) {
    float lo, hi;
    asm("mov.b64 {%0, %1}, %2;" : "=f"(lo), "=f"(hi) : "l"(v));
    return make_float2(lo, hi);
}

__global__ __launch_bounds__(256, 1)
void bvp_jet_kernel(const float* __restrict__ gx, const float* __restrict__ gy,
                    const float* __restrict__ gz, const float* __restrict__ gf,
                    const float* __restrict__ W1, const float* __restrict__ b1,
                    const float* __restrict__ W2, const float* __restrict__ b2,
                    const float* __restrict__ W3, const float* __restrict__ b3,
                    const float* __restrict__ W4, const float* __restrict__ b4,
                    float* __restrict__ out, int N)
{
    extern __shared__ float sm[];
    float* S    = sm + S_OFF;     // [256][80]  jet state, neuron-major
    float* Wsh  = sm + W_OFF;     // [32][260]  transposed W k-tile
    float* xyzf = sm + XYZF_OFF;  // [16][4]
    float* red  = sm + RED_OFF;   // [4][16][16]
    float* tot  = sm + TOT_OFF;   // [4][16]

    const int tid = threadIdx.x;
    const int cg  = tid >> 4;     // column group (0..15): neurons o0..o0+15
    const int s   = tid & 15;     // sample within block
    const int o0  = cg << 4;
    const int s5  = s * 5;
    const int n0  = blockIdx.x * BSAMP;

    // Laplacian weights (computed in double, truncated to fp32 like the ref)
    const float CX = (float)((0.5 * 0.6) * (0.5 * 0.6));   // (YC*ZC)^2
    const float CY = (float)((0.7 * 0.6) * (0.7 * 0.6));   // (XC*ZC)^2
    const float CZ = (float)((0.7 * 0.5) * (0.7 * 0.5));   // (XC*YC)^2

    // ---- load coordinates --------------------------------------------------
    if (tid < 64) {
        int ss = tid >> 2, w = tid & 3;
        int n = n0 + ss; if (n >= N) n = N - 1;
        const float* p = (w == 0) ? gx : (w == 1) ? gy : (w == 2) ? gz : gf;
        xyzf[tid] = p[n];
    }
    __syncthreads();

    // ---- layer 1 (4 -> 256), tangent pre-acts are columns of W1 ------------
    {
        float xs = xyzf[s * 4 + 0], ys = xyzf[s * 4 + 1];
        float zs = xyzf[s * 4 + 2], fs = xyzf[s * 4 + 3];
        #pragma unroll
        for (int j = 0; j < 16; ++j) {
            int o = o0 + j;
            float4 w = *(const float4*)(W1 + o * 4);
            float u  = fmaf(w.x, xs, fmaf(w.y, ys, fmaf(w.z, zs,
                        fmaf(w.w, fs, b1[o]))));
            float yv = tanhf(u);
            float sg = fmaf(-yv, yv, 1.0f);
            float g  = CX * w.x * w.x + CY * w.y * w.y + CZ * w.z * w.z;
            float* Sr = S + o * S_STRIDE + s5;
            Sr[0] = yv;
            Sr[1] = sg * w.x;
            Sr[2] = sg * w.y;
            Sr[3] = sg * w.z;
            Sr[4] = -2.0f * yv * sg * g;   // u''=0 at layer 1
        }
    }
    __syncthreads();

    // ---- hidden layers 2 and 3 (fused GEMM + jet-tanh) ----------------------
    const float* Wg_arr[2] = {W2, W3};
    const float* bg_arr[2] = {b2, b3};
    const int r32 = tid >> 3;   // tile-load row offset 0..31
    const int c4  = tid & 7;    // tile-load float4 col 0..7

    #pragma unroll 1
    for (int L = 0; L < 2; ++L) {
        const float* __restrict__ Wg = Wg_arr[L];
        const float* __restrict__ bg = bg_arr[L];

        unsigned long long acc[5][8];
        #pragma unroll
        for (int c = 0; c < 5; ++c)
            #pragma unroll
            for (int j = 0; j < 8; ++j) acc[c][j] = 0ULL;

        #pragma unroll 1
        for (int kt = 0; kt < 8; ++kt) {
            if (kt) __syncthreads();
            // cooperative load of W[:, kt*32 .. kt*32+32), transposed into Wsh[k][o]
            #pragma unroll
            for (int it = 0; it < 8; ++it) {
                int row = it * 32 + r32;
                float4 wv = *(const float4*)(Wg + row * HD + kt * 32 + c4 * 4);
                float* d = Wsh + (c4 * 4) * W_STRIDE + row;
                d[0 * W_STRIDE] = wv.x;
                d[1 * W_STRIDE] = wv.y;
                d[2 * W_STRIDE] = wv.z;
                d[3 * W_STRIDE] = wv.w;
            }
            __syncthreads();

            #pragma unroll
            for (int kk = 0; kk < 32; ++kk) {
                const float* srow = S + (kt * 32 + kk) * S_STRIDE + s5;
                unsigned long long s2[5];
                #pragma unroll
                for (int c = 0; c < 5; ++c) s2[c] = pack2(srow[c]);
                const ulonglong2* wp =
                    (const ulonglong2*)(Wsh + kk * W_STRIDE + o0);
                ulonglong2 wa = wp[0], wb = wp[1], wc = wp[2], wd = wp[3];
                unsigned long long w8[8] =
                    {wa.x, wa.y, wb.x, wb.y, wc.x, wc.y, wd.x, wd.y};
                #pragma unroll
                for (int c = 0; c < 5; ++c)
                    #pragma unroll
                    for (int j = 0; j < 8; ++j)
                        fma2(acc[c][j], w8[j], s2[c]);
            }
        }
        __syncthreads();   // everyone done reading old S

        // jet-tanh activation, entirely in registers, write new S
        #pragma unroll
        for (int j = 0; j < 8; ++j) {
            float2 uv = unpack2(acc[0][j]);
            float2 tx = unpack2(acc[1][j]);
            float2 ty = unpack2(acc[2][j]);
            float2 tz = unpack2(acc[3][j]);
            float2 qa = unpack2(acc[4][j]);
            #pragma unroll
            for (int h = 0; h < 2; ++h) {
                int o = o0 + j * 2 + h;
                float u   = (h ? uv.y : uv.x) + bg[o];
                float txv = h ? tx.y : tx.x;
                float tyv = h ? ty.y : ty.x;
                float tzv = h ? tz.y : tz.x;
                float qav = h ? qa.y : qa.x;
                float yv = tanhf(u);
                float sg = fmaf(-yv, yv, 1.0f);
                float g  = CX * txv * txv + CY * tyv * tyv + CZ * tzv * tzv;
                float* Sr = S + o * S_STRIDE + s5;
                Sr[0] = yv;
                Sr[1] = sg * txv;
                Sr[2] = sg * tyv;
                Sr[3] = sg * tzv;
                Sr[4] = fmaf(sg, qav, -2.0f * yv * sg * g);
            }
        }
        __syncthreads();
    }

    // ---- layer 4 (256 -> 2) for value and q channels ------------------------
    float p0 = 0.f, p1 = 0.f, q0 = 0.f, q1 = 0.f;
    #pragma unroll
    for (int j = 0; j < 16; ++j) {
        int o = o0 + j;
        const float* Sr = S + o * S_STRIDE + s5;
        float v = Sr[0], q = Sr[4];
        float w0 = W4[o], w1 = W4[HD + o];
        p0 = fmaf(w0, v, p0);
        p1 = fmaf(w1, v, p1);
        q0 = fmaf(w0, q, q0);
        q1 = fmaf(w1, q, q1);
    }
    red[0 * 256 + s * 16 + cg] = p0;
    red[1 * 256 + s * 16 + cg] = p1;
    red[2 * 256 + s * 16 + cg] = q0;
    red[3 * 256 + s * 16 + cg] = q1;
    __syncthreads();

    if (tid < 64) {
        int v = tid >> 4, ss = tid & 15;
        const float* rp = red + v * 256 + ss * 16;
        float t = 0.f;
        #pragma unroll
        for (int i = 0; i < 16; ++i) t += rp[i];
        tot[v * 16 + ss] = t;
    }
    __syncthreads();

    if (tid < 16) {
        int ss = tid;
        int n = n0 + ss;
        if (n < N) {
            float P0 = tot[0 * 16 + ss] + b4[0];
            float P1 = tot[1 * 16 + ss] + b4[1];
            float Q0 = tot[2 * 16 + ss];
            float Q1 = tot[3 * 16 + ss];
            float fs = xyzf[ss * 4 + 3];
            float kw = 6.283185307179586f * fmaf(fs, 500.0f, 100.0f) / 343.0f;
            float kx = 0.21f * kw;                 // XC*YC*ZC * k
            float K2 = kx * kx;
            out[n]     = 2.0f * Q0 + K2 * fmaf(2.0f, P0, 0.1f);
            out[N + n] = 1.5f * Q1 + K2 * fmaf(1.5f, P1, -0.05f);
        }
    }
}

extern "C" void kernel_launch(void* const* d_in, const int* in_sizes, int n_in,
                              void* d_out, int out_size)
{
    const float* x  = (const float*)d_in[0];
    const float* y  = (const float*)d_in[1];
    const float* z  = (const float*)d_in[2];
    const float* f  = (const float*)d_in[3];
    const float* W1 = (const float*)d_in[4];
    const float* b1 = (const float*)d_in[5];
    const float* W2 = (const float*)d_in[6];
    const float* b2 = (const float*)d_in[7];
    const float* W3 = (const float*)d_in[8];
    const float* b3 = (const float*)d_in[9];
    const float* W4 = (const float*)d_in[10];
    const float* b4 = (const float*)d_in[11];
    float* out = (float*)d_out;

    int N = in_sizes[0];
    int blocks = (N + BSAMP - 1) / BSAMP;
    size_t smem = SMEM_FLOATS * sizeof(float);

    cudaFuncSetAttribute(bvp_jet_kernel,
                         cudaFuncAttributeMaxDynamicSharedMemorySize,
                         (int)smem);
    bvp_jet_kernel<<<blocks, 256, smem>>>(x, y, z, f, W1, b1, W2, b2,
                                          W3, b3, W4, b4, out, N);
}

// round 2
// speedup vs baseline: 1.1920x; 1.1920x over previous
#include <cuda_runtime.h>

// ---------------------------------------------------------------------------
// BVP Helmholtz residual via forward-mode 2nd-order jet propagation.
// Round 2: weights pre-transposed to [k][o] in a device-global buffer and read
// directly from global/L1 (no smem staging, no intra-layer barriers), smem cut
// to 86.5KB -> 2 CTAs/SM for latency hiding. Packed fp32x2 FMA throughout.
//
// Channels per sample (C=5): [value, t_x, t_y, t_z, q] where
//   t_d  = d(h)/d(x_d), q = cx*h_xx + cy*h_yy + cz*h_zz
// tanh jet:  y = tanh(u), s = 1-y^2
//            t_d <- s*u_td
//            q   <- s*u_q - 2*y*s*(cx*u_tx^2 + cy*u_ty^2 + cz*u_tz^2)
// Residual:  re = AC*q0 + K2*(AC*p0 + A0), im = BC*q1 + K2*(BC*p1 + B0)
// ---------------------------------------------------------------------------

#define HD 256
#define BSAMP 16          // samples per block
#define S_STRIDE 80       // 16 samples * 5 channels

// smem layout (floats)
#define S_OFF    0
#define XYZF_OFF (HD * S_STRIDE)            // 20480
#define RED_OFF  (XYZF_OFF + 64)            // 20544
#define TOT_OFF  (RED_OFF + 1024)           // 21568
#define SMEM_FLOATS (TOT_OFF + 64)          // 21632 floats = 86528 B

// transposed hidden-layer weights: WT[L][k*256 + o] = W[L][o*256 + k]
__device__ float WT_buf[2][HD * HD];

__global__ __launch_bounds__(256)
void transpose_w(const float* __restrict__ W2, const float* __restrict__ W3)
{
    int t = blockIdx.x * blockDim.x + threadIdx.x;   // 0..65535
    int o = t >> 8, k = t & 255;
    WT_buf[0][k * HD + o] = W2[o * HD + k];
    WT_buf[1][k * HD + o] = W3[o * HD + k];
}

__device__ __forceinline__ unsigned long long pack2(float v) {
    unsigned long long r;
    asm("mov.b64 %0, {%1, %1};" : "=l"(r) : "f"(v));
    return r;
}
__device__ __forceinline__ void fma2(unsigned long long& d,
                                     unsigned long long a,
                                     unsigned long long b) {
    asm("fma.rn.f32x2 %0, %1, %2, %0;" : "+l"(d) : "l"(a), "l"(b));
}
__device__ __forceinline__ float2 unpack2(unsigned long long v) {
    float lo, hi;
    asm("mov.b64 {%0, %1}, %2;" : "=f"(lo), "=f"(hi) : "l"(v));
    return make_float2(lo, hi);
}

__global__ __launch_bounds__(256, 2)
void bvp_jet_kernel(const float* __restrict__ gx, const float* __restrict__ gy,
                    const float* __restrict__ gz, const float* __restrict__ gf,
                    const float* __restrict__ W1, const float* __restrict__ b1,
                    const float* __restrict__ b2, const float* __restrict__ b3,
                    const float* __restrict__ W4, const float* __restrict__ b4,
                    float* __restrict__ out, int N)
{
    extern __shared__ float sm[];
    float* S    = sm + S_OFF;     // [256][80]  jet state, neuron-major
    float* xyzf = sm + XYZF_OFF;  // [16][4]
    float* red  = sm + RED_OFF;   // [4][16][16]
    float* tot  = sm + TOT_OFF;   // [4][16]

    const int tid = threadIdx.x;
    const int cg  = tid >> 4;     // column group (0..15): neurons o0..o0+15
    const int s   = tid & 15;     // sample within block
    const int o0  = cg << 4;
    const int s5  = s * 5;
    const int n0  = blockIdx.x * BSAMP;

    const float CX = (float)((0.5 * 0.6) * (0.5 * 0.6));   // (YC*ZC)^2
    const float CY = (float)((0.7 * 0.6) * (0.7 * 0.6));   // (XC*ZC)^2
    const float CZ = (float)((0.7 * 0.5) * (0.7 * 0.5));   // (XC*YC)^2

    // ---- load coordinates --------------------------------------------------
    if (tid < 64) {
        int ss = tid >> 2, w = tid & 3;
        int n = n0 + ss; if (n >= N) n = N - 1;
        const float* p = (w == 0) ? gx : (w == 1) ? gy : (w == 2) ? gz : gf;
        xyzf[tid] = p[n];
    }
    __syncthreads();

    // ---- layer 1 (4 -> 256), tangent pre-acts are columns of W1 ------------
    {
        float xs = xyzf[s * 4 + 0], ys = xyzf[s * 4 + 1];
        float zs = xyzf[s * 4 + 2], fs = xyzf[s * 4 + 3];
        #pragma unroll
        for (int j = 0; j < 16; ++j) {
            int o = o0 + j;
            float4 w = *(const float4*)(W1 + o * 4);
            float u  = fmaf(w.x, xs, fmaf(w.y, ys, fmaf(w.z, zs,
                        fmaf(w.w, fs, b1[o]))));
            float yv = tanhf(u);
            float sg = fmaf(-yv, yv, 1.0f);
            float g  = CX * w.x * w.x + CY * w.y * w.y + CZ * w.z * w.z;
            float* Sr = S + o * S_STRIDE + s5;
            Sr[0] = yv;
            Sr[1] = sg * w.x;
            Sr[2] = sg * w.y;
            Sr[3] = sg * w.z;
            Sr[4] = -2.0f * yv * sg * g;   // u''=0 at layer 1
        }
    }
    __syncthreads();

    // ---- hidden layers 2 and 3: GEMM from global WT + jet-tanh -------------
    #pragma unroll 1
    for (int L = 0; L < 2; ++L) {
        const float* __restrict__ Wt = WT_buf[L];
        const float* __restrict__ bg = L ? b3 : b2;

        unsigned long long acc[5][8];
        #pragma unroll
        for (int c = 0; c < 5; ++c)
            #pragma unroll
            for (int j = 0; j < 8; ++j) acc[c][j] = 0ULL;

        #pragma unroll 4
        for (int k = 0; k < HD; ++k) {
            // 16 consecutive weights for this thread's neuron group
            const ulonglong2* wp = (const ulonglong2*)(Wt + (k << 8) + o0);
            ulonglong2 wa = wp[0], wb = wp[1], wc = wp[2], wd = wp[3];
            // 5 jet channels of sample s, neuron k (broadcast across 16 lanes)
            const float* srow = S + k * S_STRIDE + s5;
            unsigned long long s2[5];
            #pragma unroll
            for (int c = 0; c < 5; ++c) s2[c] = pack2(srow[c]);
            unsigned long long w8[8] =
                {wa.x, wa.y, wb.x, wb.y, wc.x, wc.y, wd.x, wd.y};
            #pragma unroll
            for (int c = 0; c < 5; ++c)
                #pragma unroll
                for (int j = 0; j < 8; ++j)
                    fma2(acc[c][j], w8[j], s2[c]);
        }
        __syncthreads();   // everyone done reading old S

        // jet-tanh activation, entirely in registers, write new S
        #pragma unroll
        for (int j = 0; j < 8; ++j) {
            float2 uv = unpack2(acc[0][j]);
            float2 tx = unpack2(acc[1][j]);
            float2 ty = unpack2(acc[2][j]);
            float2 tz = unpack2(acc[3][j]);
            float2 qa = unpack2(acc[4][j]);
            #pragma unroll
            for (int h = 0; h < 2; ++h) {
                int o = o0 + j * 2 + h;
                float u   = (h ? uv.y : uv.x) + bg[o];
                float txv = h ? tx.y : tx.x;
                float tyv = h ? ty.y : ty.x;
                float tzv = h ? tz.y : tz.x;
                float qav = h ? qa.y : qa.x;
                float yv = tanhf(u);
                float sg = fmaf(-yv, yv, 1.0f);
                float g  = CX * txv * txv + CY * tyv * tyv + CZ * tzv * tzv;
                float* Sr = S + o * S_STRIDE + s5;
                Sr[0] = yv;
                Sr[1] = sg * txv;
                Sr[2] = sg * tyv;
                Sr[3] = sg * tzv;
                Sr[4] = fmaf(sg, qav, -2.0f * yv * sg * g);
            }
        }
        __syncthreads();
    }

    // ---- layer 4 (256 -> 2) for value and q channels ------------------------
    float p0 = 0.f, p1 = 0.f, q0 = 0.f, q1 = 0.f;
    #pragma unroll
    for (int j = 0; j < 16; ++j) {
        int o = o0 + j;
        const float* Sr = S + o * S_STRIDE + s5;
        float v = Sr[0], q = Sr[4];
        float w0 = W4[o], w1 = W4[HD + o];
        p0 = fmaf(w0, v, p0);
        p1 = fmaf(w1, v, p1);
        q0 = fmaf(w0, q, q0);
        q1 = fmaf(w1, q, q1);
    }
    red[0 * 256 + s * 16 + cg] = p0;
    red[1 * 256 + s * 16 + cg] = p1;
    red[2 * 256 + s * 16 + cg] = q0;
    red[3 * 256 + s * 16 + cg] = q1;
    __syncthreads();

    if (tid < 64) {
        int v = tid >> 4, ss = tid & 15;
        const float* rp = red + v * 256 + ss * 16;
        float t = 0.f;
        #pragma unroll
        for (int i = 0; i < 16; ++i) t += rp[i];
        tot[v * 16 + ss] = t;
    }
    __syncthreads();

    if (tid < 16) {
        int ss = tid;
        int n = n0 + ss;
        if (n < N) {
            float P0 = tot[0 * 16 + ss] + b4[0];
            float P1 = tot[1 * 16 + ss] + b4[1];
            float Q0 = tot[2 * 16 + ss];
            float Q1 = tot[3 * 16 + ss];
            float fs = xyzf[ss * 4 + 3];
            float kw = 6.283185307179586f * fmaf(fs, 500.0f, 100.0f) / 343.0f;
            float kx = 0.21f * kw;                 // XC*YC*ZC * k
            float K2 = kx * kx;
            out[n]     = 2.0f * Q0 + K2 * fmaf(2.0f, P0, 0.1f);
            out[N + n] = 1.5f * Q1 + K2 * fmaf(1.5f, P1, -0.05f);
        }
    }
}

extern "C" void kernel_launch(void* const* d_in, const int* in_sizes, int n_in,
                              void* d_out, int out_size)
{
    const float* x  = (const float*)d_in[0];
    const float* y  = (const float*)d_in[1];
    const float* z  = (const float*)d_in[2];
    const float* f  = (const float*)d_in[3];
    const float* W1 = (const float*)d_in[4];
    const float* b1 = (const float*)d_in[5];
    const float* W2 = (const float*)d_in[6];
    const float* b2 = (const float*)d_in[7];
    const float* W3 = (const float*)d_in[8];
    const float* b3 = (const float*)d_in[9];
    const float* W4 = (const float*)d_in[10];
    const float* b4 = (const float*)d_in[11];
    float* out = (float*)d_out;

    int N = in_sizes[0];
    int blocks = (N + BSAMP - 1) / BSAMP;
    size_t smem = SMEM_FLOATS * sizeof(float);

    transpose_w<<<HD, 256>>>(W2, W3);

    cudaFuncSetAttribute(bvp_jet_kernel,
                         cudaFuncAttributeMaxDynamicSharedMemorySize,
                         (int)smem);
    bvp_jet_kernel<<<blocks, 256, smem>>>(x, y, z, f, W1, b1, b2,
                                          b3, W4, b4, out, N);
}

// round 4
// speedup vs baseline: 1.9843x; 1.6646x over previous
#include <cuda_runtime.h>
#include <cuda_bf16.h>
#include <cstdint>

// ---------------------------------------------------------------------------
// BVP Helmholtz residual via 2nd-order jet propagation on mma.sync (bf16 HMMA,
// 3-pass hi/lo split for fp32-grade accuracy). Baseline PTX only (compute_103).
//
// Per CTA: 12 samples -> 60 jet rows (value,tx,ty,tz,q) padded to M=64.
// Layer GEMM: D[m][n] = sum_k A[m][k] B[n][k]; A=jets bf16 split in SMEM,
// B=weights bf16 split streamed global->SMEM via cp.async (k-chunks of 32,
// double buffered, cross-layer prefetch). Epilogue: D->SMEM, jet-tanh fp32,
// re-split to bf16 A. Final layer (256->2) fused into last epilogue.
// ---------------------------------------------------------------------------

#define HD 256
#define SB 12          // samples per CTA
#define M_ROWS 64      // 60 used
#define AROW 528       // A row stride bytes (264 bf16)
#define ASPLIT 33792   // 64*528
#define BROW 80        // B stage row stride bytes (40 bf16)
#define BSPLIT 20480   // 256*80
#define BBUF 40960     // 2 splits
#define DROW 260       // D row stride (floats)

#define A_OFF 0
#define B_OFF 67584
#define D_OFF 149504
#define XYZF_OFF 216064
#define PART_OFF 216256
#define SMEM_BYTES 217856

// prepped weights: [layer][split hi/lo][n][k] bf16
__device__ __align__(16) __nv_bfloat16 Wbf[2][2][HD][HD];

__global__ __launch_bounds__(256)
void prep_weights(const float* __restrict__ W2, const float* __restrict__ W3)
{
    int t = blockIdx.x * 256 + threadIdx.x;      // 131072
    int layer = t >> 16, n = (t >> 8) & 255, k = t & 255;
    float w = (layer ? W3 : W2)[n * HD + k];
    __nv_bfloat16 h = __float2bfloat16(w);
    __nv_bfloat16 l = __float2bfloat16(w - __bfloat162float(h));
    Wbf[layer][0][n][k] = h;
    Wbf[layer][1][n][k] = l;
}

__device__ __forceinline__ uint32_t smem_u32(const void* p) {
    uint32_t a;
    asm("{ .reg .u64 t; cvta.to.shared.u64 t, %1; cvt.u32.u64 %0, t; }"
        : "=r"(a) : "l"(p));
    return a;
}
__device__ __forceinline__ void ldsm4(uint32_t* r, uint32_t a) {
    asm volatile("ldmatrix.sync.aligned.m8n8.x4.shared.b16 {%0,%1,%2,%3}, [%4];"
                 : "=r"(r[0]), "=r"(r[1]), "=r"(r[2]), "=r"(r[3]) : "r"(a));
}
__device__ __forceinline__ void ldsm2(uint32_t* r, uint32_t a) {
    asm volatile("ldmatrix.sync.aligned.m8n8.x2.shared.b16 {%0,%1}, [%2];"
                 : "=r"(r[0]), "=r"(r[1]) : "r"(a));
}
__device__ __forceinline__ void mma_bf16(float* c, const uint32_t* a,
                                         const uint32_t* b) {
    asm volatile("mma.sync.aligned.m16n8k16.row.col.f32.bf16.bf16.f32 "
                 "{%0,%1,%2,%3}, {%4,%5,%6,%7}, {%8,%9}, {%0,%1,%2,%3};"
                 : "+f"(c[0]), "+f"(c[1]), "+f"(c[2]), "+f"(c[3])
                 : "r"(a[0]), "r"(a[1]), "r"(a[2]), "r"(a[3]),
                   "r"(b[0]), "r"(b[1]));
}
__device__ __forceinline__ void cp16(uint32_t sa, const void* ga) {
    asm volatile("cp.async.cg.shared.global [%0], [%1], 16;"
                 :: "r"(sa), "l"(__cvta_generic_to_global(ga)) : "memory");
}
#define CP_COMMIT() asm volatile("cp.async.commit_group;" ::: "memory")
#define CP_WAIT(n)  asm volatile("cp.async.wait_group %0;" :: "n"(n) : "memory")

__global__ __launch_bounds__(256, 1)
void bvp_mma_kernel(const float* __restrict__ gx, const float* __restrict__ gy,
                    const float* __restrict__ gz, const float* __restrict__ gf,
                    const float* __restrict__ W1, const float* __restrict__ b1,
                    const float* __restrict__ b2, const float* __restrict__ b3,
                    const float* __restrict__ W4, const float* __restrict__ b4,
                    float* __restrict__ out, int N)
{
    extern __shared__ char sm[];
    const uint32_t smb = smem_u32(sm);
    float* Dst  = (float*)(sm + D_OFF);
    float* xyzf = (float*)(sm + XYZF_OFF);
    float* part = (float*)(sm + PART_OFF);   // [12][8][4]

    const int tid = threadIdx.x;
    const int wid = tid >> 5;
    const int lid = tid & 31;
    const int n0w = wid << 5;
    const int n0  = blockIdx.x * SB;

    const float CX = (float)((0.5 * 0.6) * (0.5 * 0.6));
    const float CY = (float)((0.7 * 0.6) * (0.7 * 0.6));
    const float CZ = (float)((0.7 * 0.5) * (0.7 * 0.5));

    // ---- stage issuance: copy B k-chunk (32 k) of layer L into buffer ------
    auto issue_stage = [&](int L, int kc, int buf) {
        #pragma unroll
        for (int j = 0; j < 8; ++j) {
            int i = tid + (j << 8);              // 0..2047
            int split = i >> 10;
            int n = (i >> 2) & 255;
            int seg = i & 3;
            uint32_t sa = smb + B_OFF + buf * BBUF + split * BSPLIT +
                          n * BROW + seg * 16;
            cp16(sa, &Wbf[L][split][n][kc * 32 + seg * 8]);
        }
        CP_COMMIT();
    };

    // write one fp32 value into A as bf16 hi/lo
    auto storeA = [&](int m, int k, float v) {
        __nv_bfloat16 h = __float2bfloat16(v);
        __nv_bfloat16 l = __float2bfloat16(v - __bfloat162float(h));
        *(__nv_bfloat16*)(sm + A_OFF + m * AROW + k * 2) = h;
        *(__nv_bfloat16*)(sm + A_OFF + ASPLIT + m * AROW + k * 2) = l;
    };

    // prefetch first two B stages of layer 0 immediately
    issue_stage(0, 0, 0);
    issue_stage(0, 1, 1);

    // coords
    if (tid < 48) {
        int ss = tid >> 2, w = tid & 3;
        int n = n0 + ss; if (n >= N) n = N - 1;
        const float* p = (w == 0) ? gx : (w == 1) ? gy : (w == 2) ? gz : gf;
        xyzf[tid] = p[n];
    }
    // zero pad rows 60..63 of A (both splits)
    for (int i = tid; i < 4 * 264; i += 256) {
        int m = 60 + i / 264, k = i % 264;
        *(__nv_bfloat16*)(sm + A_OFF + m * AROW + k * 2) = __float2bfloat16(0.f);
        *(__nv_bfloat16*)(sm + A_OFF + ASPLIT + m * AROW + k * 2) =
            __float2bfloat16(0.f);
    }
    __syncthreads();

    // ---- layer 1: 4 -> 256, jets analytically -----------------------------
    #pragma unroll 1
    for (int s = 0; s < SB; ++s) {
        int k = tid;                             // neuron index
        float4 w = *(const float4*)(W1 + k * 4);
        float u = fmaf(w.x, xyzf[s * 4 + 0], fmaf(w.y, xyzf[s * 4 + 1],
                  fmaf(w.z, xyzf[s * 4 + 2], fmaf(w.w, xyzf[s * 4 + 3],
                  b1[k]))));
        float yv = tanhf(u);
        float sg = fmaf(-yv, yv, 1.0f);
        float g  = CX * w.x * w.x + CY * w.y * w.y + CZ * w.z * w.z;
        int m = s * 5;
        storeA(m + 0, k, yv);
        storeA(m + 1, k, sg * w.x);
        storeA(m + 2, k, sg * w.y);
        storeA(m + 3, k, sg * w.z);
        storeA(m + 4, k, -2.0f * yv * sg * g);
    }
    __syncthreads();

    const int g = lid >> 2, cc = (lid & 3) << 1;

    // ---- hidden layers 2,3 --------------------------------------------------
    #pragma unroll 1
    for (int L = 0; L < 2; ++L) {
        float acc[4][4][4];
        #pragma unroll
        for (int mt = 0; mt < 4; ++mt)
            #pragma unroll
            for (int nt = 0; nt < 4; ++nt)
                #pragma unroll
                for (int r = 0; r < 4; ++r) acc[mt][nt][r] = 0.f;

        #pragma unroll 1
        for (int kc = 0; kc < 8; ++kc) {
            if (L == 1 && kc == 7) { CP_WAIT(0); } else { CP_WAIT(1); }
            __syncthreads();
            int buf = kc & 1;

            #pragma unroll
            for (int ks = 0; ks < 2; ++ks) {
                int kl0 = ks << 4;
                uint32_t bf[2][4][2];
                #pragma unroll
                for (int nt = 0; nt < 4; ++nt) {
                    uint32_t ba = smb + B_OFF + buf * BBUF +
                                  (n0w + (nt << 3) + (lid & 7)) * BROW +
                                  (kl0 + (lid & 8)) * 2;
                    ldsm2(bf[0][nt], ba);
                    ldsm2(bf[1][nt], ba + BSPLIT);
                }
                #pragma unroll
                for (int mt = 0; mt < 4; ++mt) {
                    uint32_t aa = smb + A_OFF +
                                  ((mt << 4) + (lid & 15)) * AROW +
                                  (kc * 32 + kl0 + ((lid >> 4) << 3)) * 2;
                    uint32_t ah[4], al[4];
                    ldsm4(ah, aa);
                    ldsm4(al, aa + ASPLIT);
                    #pragma unroll
                    for (int nt = 0; nt < 4; ++nt) {
                        mma_bf16(acc[mt][nt], ah, bf[0][nt]);  // hi*hi
                        mma_bf16(acc[mt][nt], al, bf[0][nt]);  // lo*hi
                        mma_bf16(acc[mt][nt], ah, bf[1][nt]);  // hi*lo
                    }
                }
            }
            __syncthreads();
            if (kc + 2 < 8)      issue_stage(L, kc + 2, buf);
            else if (L == 0)     issue_stage(1, kc - 6, buf);
        }

        // ---- stage D to smem -------------------------------------------------
        #pragma unroll
        for (int mt = 0; mt < 4; ++mt)
            #pragma unroll
            for (int nt = 0; nt < 4; ++nt) {
                int m0 = (mt << 4), nn = n0w + (nt << 3) + cc;
                *(float2*)(Dst + (m0 + g) * DROW + nn) =
                    make_float2(acc[mt][nt][0], acc[mt][nt][1]);
                *(float2*)(Dst + (m0 + g + 8) * DROW + nn) =
                    make_float2(acc[mt][nt][2], acc[mt][nt][3]);
            }
        __syncthreads();

        // ---- activation epilogue --------------------------------------------
        if (L == 0) {
            float bn = b2[tid];
            #pragma unroll 1
            for (int s = 0; s < SB; ++s) {
                int mr = s * 5;
                float u  = Dst[(mr + 0) * DROW + tid] + bn;
                float tx = Dst[(mr + 1) * DROW + tid];
                float ty = Dst[(mr + 2) * DROW + tid];
                float tz = Dst[(mr + 3) * DROW + tid];
                float qa = Dst[(mr + 4) * DROW + tid];
                float yv = tanhf(u);
                float sg = fmaf(-yv, yv, 1.0f);
                float gq = CX * tx * tx + CY * ty * ty + CZ * tz * tz;
                storeA(mr + 0, tid, yv);
                storeA(mr + 1, tid, sg * tx);
                storeA(mr + 2, tid, sg * ty);
                storeA(mr + 3, tid, sg * tz);
                storeA(mr + 4, tid, fmaf(sg, qa, -2.0f * yv * sg * gq));
            }
            __syncthreads();
        } else {
            float bn  = b3[tid];
            float w40 = W4[tid], w41 = W4[HD + tid];
            #pragma unroll 1
            for (int s = 0; s < SB; ++s) {
                int mr = s * 5;
                float u  = Dst[(mr + 0) * DROW + tid] + bn;
                float tx = Dst[(mr + 1) * DROW + tid];
                float ty = Dst[(mr + 2) * DROW + tid];
                float tz = Dst[(mr + 3) * DROW + tid];
                float qa = Dst[(mr + 4) * DROW + tid];
                float yv = tanhf(u);
                float sg = fmaf(-yv, yv, 1.0f);
                float gq = CX * tx * tx + CY * ty * ty + CZ * tz * tz;
                float qn = fmaf(sg, qa, -2.0f * yv * sg * gq);
                float v0 = w40 * yv, v1 = w41 * yv;
                float v2 = w40 * qn, v3 = w41 * qn;
                #pragma unroll
                for (int o = 16; o; o >>= 1) {
                    v0 += __shfl_xor_sync(0xFFFFFFFFu, v0, o);
                    v1 += __shfl_xor_sync(0xFFFFFFFFu, v1, o);
                    v2 += __shfl_xor_sync(0xFFFFFFFFu, v2, o);
                    v3 += __shfl_xor_sync(0xFFFFFFFFu, v3, o);
                }
                if (lid == 0) {
                    float* pp = part + (s * 8 + wid) * 4;
                    pp[0] = v0; pp[1] = v1; pp[2] = v2; pp[3] = v3;
                }
            }
            __syncthreads();
        }
    }

    // ---- residual output -----------------------------------------------------
    if (tid < SB) {
        int n = n0 + tid;
        if (n < N) {
            float P0 = 0.f, P1 = 0.f, Q0 = 0.f, Q1 = 0.f;
            #pragma unroll
            for (int w = 0; w < 8; ++w) {
                const float* pp = part + (tid * 8 + w) * 4;
                P0 += pp[0]; P1 += pp[1]; Q0 += pp[2]; Q1 += pp[3];
            }
            P0 += b4[0]; P1 += b4[1];
            float fs = xyzf[tid * 4 + 3];
            float kw = 6.283185307179586f * fmaf(fs, 500.0f, 100.0f) / 343.0f;
            float kx = 0.21f * kw;
            float K2 = kx * kx;
            out[n]     = 2.0f * Q0 + K2 * fmaf(2.0f, P0, 0.1f);
            out[N + n] = 1.5f * Q1 + K2 * fmaf(1.5f, P1, -0.05f);
        }
    }
}

extern "C" void kernel_launch(void* const* d_in, const int* in_sizes, int n_in,
                              void* d_out, int out_size)
{
    const float* x  = (const float*)d_in[0];
    const float* y  = (const float*)d_in[1];
    const float* z  = (const float*)d_in[2];
    const float* f  = (const float*)d_in[3];
    const float* W1 = (const float*)d_in[4];
    const float* b1 = (const float*)d_in[5];
    const float* W2 = (const float*)d_in[6];
    const float* b2 = (const float*)d_in[7];
    const float* W3 = (const float*)d_in[8];
    const float* b3 = (const float*)d_in[9];
    const float* W4 = (const float*)d_in[10];
    const float* b4 = (const float*)d_in[11];
    float* out = (float*)d_out;

    int N = in_sizes[0];
    prep_weights<<<512, 256>>>(W2, W3);

    cudaFuncSetAttribute(bvp_mma_kernel,
                         cudaFuncAttributeMaxDynamicSharedMemorySize,
                         SMEM_BYTES);
    int blocks = (N + SB - 1) / SB;
    bvp_mma_kernel<<<blocks, 256, SMEM_BYTES>>>(x, y, z, f, W1, b1, b2, b3,
                                                W4, b4, out, N);
}

// round 5
// speedup vs baseline: 2.5263x; 1.2732x over previous
#include <cuda_runtime.h>
#include <cuda_bf16.h>
#include <cstdint>

// ---------------------------------------------------------------------------
// BVP Helmholtz residual via 2nd-order jet propagation on mma.sync bf16 HMMA
// (3-pass hi/lo split). Round 5: 512 threads, M=128 (24 samples/CTA),
// 16 warps = 2 m-groups x 8 n-slices -> 4 HMMA-issuing warps/SMSP.
// D staging aliases the A region row-for-row (in-place jet exchange).
// ---------------------------------------------------------------------------

#define HD 256
#define SB 24          // samples per CTA
#define AROW 1040      // A row bytes: hi[0,512) pad lo[528,1040)  == D row
#define BROW 80        // B stage row stride bytes
#define BSPLIT 20480   // 256*80
#define BBUF 40960     // 2 splits
#define DROW 260       // D row stride in floats (= 1040 B)

#define A_OFF 0
#define B_OFF 133120   // 128*1040
#define XYZF_OFF 215040
#define PART_OFF 215424
#define SMEM_BYTES 218624

// prepped weights: [layer][split hi/lo][n][k] bf16
__device__ __align__(16) __nv_bfloat16 Wbf[2][2][HD][HD];

__global__ __launch_bounds__(256)
void prep_weights(const float* __restrict__ W2, const float* __restrict__ W3)
{
    int t = blockIdx.x * 256 + threadIdx.x;      // 131072
    int layer = t >> 16, n = (t >> 8) & 255, k = t & 255;
    float w = (layer ? W3 : W2)[n * HD + k];
    __nv_bfloat16 h = __float2bfloat16(w);
    __nv_bfloat16 l = __float2bfloat16(w - __bfloat162float(h));
    Wbf[layer][0][n][k] = h;
    Wbf[layer][1][n][k] = l;
}

__device__ __forceinline__ uint32_t smem_u32(const void* p) {
    uint32_t a;
    asm("{ .reg .u64 t; cvta.to.shared.u64 t, %1; cvt.u32.u64 %0, t; }"
        : "=r"(a) : "l"(p));
    return a;
}
__device__ __forceinline__ void ldsm4(uint32_t* r, uint32_t a) {
    asm volatile("ldmatrix.sync.aligned.m8n8.x4.shared.b16 {%0,%1,%2,%3}, [%4];"
                 : "=r"(r[0]), "=r"(r[1]), "=r"(r[2]), "=r"(r[3]) : "r"(a));
}
__device__ __forceinline__ void ldsm2(uint32_t* r, uint32_t a) {
    asm volatile("ldmatrix.sync.aligned.m8n8.x2.shared.b16 {%0,%1}, [%2];"
                 : "=r"(r[0]), "=r"(r[1]) : "r"(a));
}
__device__ __forceinline__ void mma_bf16(float* c, const uint32_t* a,
                                         const uint32_t* b) {
    asm volatile("mma.sync.aligned.m16n8k16.row.col.f32.bf16.bf16.f32 "
                 "{%0,%1,%2,%3}, {%4,%5,%6,%7}, {%8,%9}, {%0,%1,%2,%3};"
                 : "+f"(c[0]), "+f"(c[1]), "+f"(c[2]), "+f"(c[3])
                 : "r"(a[0]), "r"(a[1]), "r"(a[2]), "r"(a[3]),
                   "r"(b[0]), "r"(b[1]));
}
__device__ __forceinline__ void cp16(uint32_t sa, const void* ga) {
    asm volatile("cp.async.cg.shared.global [%0], [%1], 16;"
                 :: "r"(sa), "l"(__cvta_generic_to_global(ga)) : "memory");
}
#define CP_COMMIT() asm volatile("cp.async.commit_group;" ::: "memory")
#define CP_WAIT(n)  asm volatile("cp.async.wait_group %0;" :: "n"(n) : "memory")

__global__ __launch_bounds__(512, 1)
void bvp_mma_kernel(const float* __restrict__ gx, const float* __restrict__ gy,
                    const float* __restrict__ gz, const float* __restrict__ gf,
                    const float* __restrict__ W1, const float* __restrict__ b1,
                    const float* __restrict__ b2, const float* __restrict__ b3,
                    const float* __restrict__ W4, const float* __restrict__ b4,
                    float* __restrict__ out, int N)
{
    extern __shared__ char sm[];
    const uint32_t smb = smem_u32(sm);
    float* Dst  = (float*)(sm + A_OFF);       // aliases A region, row-for-row
    float* xyzf = (float*)(sm + XYZF_OFF);
    float* part = (float*)(sm + PART_OFF);    // [24][8][4]

    const int tid = threadIdx.x;
    const int wid = tid >> 5;
    const int lid = tid & 31;
    const int mg  = wid >> 3;                 // m-group 0/1 (rows mg*64..+64)
    const int ng  = wid & 7;                  // n-slice (cols ng*32..+32)
    const int n0w = ng << 5;
    const int n0  = blockIdx.x * SB;

    const float CX = (float)((0.5 * 0.6) * (0.5 * 0.6));
    const float CY = (float)((0.7 * 0.6) * (0.7 * 0.6));
    const float CZ = (float)((0.7 * 0.5) * (0.7 * 0.5));

    auto issue_stage = [&](int L, int kc, int buf) {
        #pragma unroll
        for (int j = 0; j < 4; ++j) {
            int i = tid + (j << 9);              // 0..2047
            int split = i >> 10;
            int n = (i >> 2) & 255;
            int seg = i & 3;
            uint32_t sa = smb + B_OFF + buf * BBUF + split * BSPLIT +
                          n * BROW + seg * 16;
            cp16(sa, &Wbf[L][split][n][kc * 32 + seg * 8]);
        }
        CP_COMMIT();
    };

    auto storeA = [&](int m, int k, float v) {
        __nv_bfloat16 h = __float2bfloat16(v);
        __nv_bfloat16 l = __float2bfloat16(v - __bfloat162float(h));
        char* base = sm + A_OFF + m * AROW + k * 2;
        *(__nv_bfloat16*)(base)       = h;
        *(__nv_bfloat16*)(base + 528) = l;
    };

    // prefetch first two B stages of layer 0
    issue_stage(0, 0, 0);
    issue_stage(0, 1, 1);

    // coords
    if (tid < 96) {
        int ss = tid >> 2, w = tid & 3;
        int n = n0 + ss; if (n >= N) n = N - 1;
        const float* p = (w == 0) ? gx : (w == 1) ? gy : (w == 2) ? gz : gf;
        xyzf[tid] = p[n];
    }
    __syncthreads();

    // ---- layer 1: 4 -> 256, jets analytically ------------------------------
    #pragma unroll 1
    for (int it = 0; it < 12; ++it) {
        int idx = tid + (it << 9);               // 24*256 = 6144 items
        int s = idx >> 8, k = idx & 255;
        float4 w = *(const float4*)(W1 + k * 4);
        float u = fmaf(w.x, xyzf[s * 4 + 0], fmaf(w.y, xyzf[s * 4 + 1],
                  fmaf(w.z, xyzf[s * 4 + 2], fmaf(w.w, xyzf[s * 4 + 3],
                  b1[k]))));
        float yv = tanhf(u);
        float sg = fmaf(-yv, yv, 1.0f);
        float g  = CX * w.x * w.x + CY * w.y * w.y + CZ * w.z * w.z;
        int m = s * 5;
        storeA(m + 0, k, yv);
        storeA(m + 1, k, sg * w.x);
        storeA(m + 2, k, sg * w.y);
        storeA(m + 3, k, sg * w.z);
        storeA(m + 4, k, -2.0f * yv * sg * g);
    }
    __syncthreads();

    const int g = lid >> 2, cc = (lid & 3) << 1;

    // ---- hidden layers 2,3 --------------------------------------------------
    #pragma unroll 1
    for (int L = 0; L < 2; ++L) {
        float acc[4][4][4];
        #pragma unroll
        for (int mt = 0; mt < 4; ++mt)
            #pragma unroll
            for (int nt = 0; nt < 4; ++nt)
                #pragma unroll
                for (int r = 0; r < 4; ++r) acc[mt][nt][r] = 0.f;

        #pragma unroll 1
        for (int kc = 0; kc < 8; ++kc) {
            if (L == 1 && kc == 7) { CP_WAIT(0); } else { CP_WAIT(1); }
            __syncthreads();
            int buf = kc & 1;

            #pragma unroll
            for (int ks = 0; ks < 2; ++ks) {
                int kl0 = ks << 4;
                uint32_t bf[2][4][2];
                #pragma unroll
                for (int nt = 0; nt < 4; ++nt) {
                    uint32_t ba = smb + B_OFF + buf * BBUF +
                                  (n0w + (nt << 3) + (lid & 7)) * BROW +
                                  (kl0 + (lid & 8)) * 2;
                    ldsm2(bf[0][nt], ba);
                    ldsm2(bf[1][nt], ba + BSPLIT);
                }
                #pragma unroll
                for (int mt = 0; mt < 4; ++mt) {
                    int row = (mg << 6) + (mt << 4) + (lid & 15);
                    uint32_t aa = smb + A_OFF + row * AROW +
                                  (kc * 32 + kl0 + ((lid >> 4) << 3)) * 2;
                    uint32_t ah[4], al[4];
                    ldsm4(ah, aa);
                    ldsm4(al, aa + 528);
                    #pragma unroll
                    for (int nt = 0; nt < 4; ++nt) {
                        mma_bf16(acc[mt][nt], ah, bf[0][nt]);  // hi*hi
                        mma_bf16(acc[mt][nt], al, bf[0][nt]);  // lo*hi
                        mma_bf16(acc[mt][nt], ah, bf[1][nt]);  // hi*lo
                    }
                }
            }
            __syncthreads();
            if (kc + 2 < 8)      issue_stage(L, kc + 2, buf);
            else if (L == 0)     issue_stage(1, kc - 6, buf);
        }

        // ---- stage acc into D (aliases dead A rows) --------------------------
        #pragma unroll
        for (int mt = 0; mt < 4; ++mt)
            #pragma unroll
            for (int nt = 0; nt < 4; ++nt) {
                int m0 = (mg << 6) + (mt << 4), nn = n0w + (nt << 3) + cc;
                *(float2*)(Dst + (m0 + g) * DROW + nn) =
                    make_float2(acc[mt][nt][0], acc[mt][nt][1]);
                *(float2*)(Dst + (m0 + g + 8) * DROW + nn) =
                    make_float2(acc[mt][nt][2], acc[mt][nt][3]);
            }
        __syncthreads();

        // ---- activation epilogue (in-place D -> new A exchange) --------------
        const int sg2 = tid >> 8;          // sample group 0/1
        const int nn  = tid & 255;
        if (L == 0) {
            float bn = b2[nn];
            #pragma unroll 1
            for (int s12 = 0; s12 < 12; ++s12) {
                int s = sg2 * 12 + s12, mr = s * 5;
                float u  = Dst[(mr + 0) * DROW + nn] + bn;
                float tx = Dst[(mr + 1) * DROW + nn];
                float ty = Dst[(mr + 2) * DROW + nn];
                float tz = Dst[(mr + 3) * DROW + nn];
                float qa = Dst[(mr + 4) * DROW + nn];
                __syncthreads();           // all reads of these rows done
                float yv = tanhf(u);
                float sgm = fmaf(-yv, yv, 1.0f);
                float gq = CX * tx * tx + CY * ty * ty + CZ * tz * tz;
                storeA(mr + 0, nn, yv);
                storeA(mr + 1, nn, sgm * tx);
                storeA(mr + 2, nn, sgm * ty);
                storeA(mr + 3, nn, sgm * tz);
                storeA(mr + 4, nn, fmaf(sgm, qa, -2.0f * yv * sgm * gq));
            }
            __syncthreads();
        } else {
            float bn  = b3[nn];
            float w40 = W4[nn], w41 = W4[HD + nn];
            #pragma unroll 1
            for (int s12 = 0; s12 < 12; ++s12) {
                int s = sg2 * 12 + s12, mr = s * 5;
                float u  = Dst[(mr + 0) * DROW + nn] + bn;
                float tx = Dst[(mr + 1) * DROW + nn];
                float ty = Dst[(mr + 2) * DROW + nn];
                float tz = Dst[(mr + 3) * DROW + nn];
                float qa = Dst[(mr + 4) * DROW + nn];
                float yv = tanhf(u);
                float sgm = fmaf(-yv, yv, 1.0f);
                float gq = CX * tx * tx + CY * ty * ty + CZ * tz * tz;
                float qn = fmaf(sgm, qa, -2.0f * yv * sgm * gq);
                float v0 = w40 * yv, v1 = w41 * yv;
                float v2 = w40 * qn, v3 = w41 * qn;
                #pragma unroll
                for (int o = 16; o; o >>= 1) {
                    v0 += __shfl_xor_sync(0xFFFFFFFFu, v0, o);
                    v1 += __shfl_xor_sync(0xFFFFFFFFu, v1, o);
                    v2 += __shfl_xor_sync(0xFFFFFFFFu, v2, o);
                    v3 += __shfl_xor_sync(0xFFFFFFFFu, v3, o);
                }
                if (lid == 0) {
                    float* pp = part + (s * 8 + (wid & 7)) * 4;
                    pp[0] = v0; pp[1] = v1; pp[2] = v2; pp[3] = v3;
                }
            }
            __syncthreads();
        }
    }

    // ---- residual output -----------------------------------------------------
    if (tid < SB) {
        int n = n0 + tid;
        if (n < N) {
            float P0 = 0.f, P1 = 0.f, Q0 = 0.f, Q1 = 0.f;
            #pragma unroll
            for (int w = 0; w < 8; ++w) {
                const float* pp = part + (tid * 8 + w) * 4;
                P0 += pp[0]; P1 += pp[1]; Q0 += pp[2]; Q1 += pp[3];
            }
            P0 += b4[0]; P1 += b4[1];
            float fs = xyzf[tid * 4 + 3];
            float kw = 6.283185307179586f * fmaf(fs, 500.0f, 100.0f) / 343.0f;
            float kx = 0.21f * kw;
            float K2 = kx * kx;
            out[n]     = 2.0f * Q0 + K2 * fmaf(2.0f, P0, 0.1f);
            out[N + n] = 1.5f * Q1 + K2 * fmaf(1.5f, P1, -0.05f);
        }
    }
}

extern "C" void kernel_launch(void* const* d_in, const int* in_sizes, int n_in,
                              void* d_out, int out_size)
{
    const float* x  = (const float*)d_in[0];
    const float* y  = (const float*)d_in[1];
    const float* z  = (const float*)d_in[2];
    const float* f  = (const float*)d_in[3];
    const float* W1 = (const float*)d_in[4];
    const float* b1 = (const float*)d_in[5];
    const float* W2 = (const float*)d_in[6];
    const float* b2 = (const float*)d_in[7];
    const float* W3 = (const float*)d_in[8];
    const float* b3 = (const float*)d_in[9];
    const float* W4 = (const float*)d_in[10];
    const float* b4 = (const float*)d_in[11];
    float* out = (float*)d_out;

    int N = in_sizes[0];
    prep_weights<<<512, 256>>>(W2, W3);

    cudaFuncSetAttribute(bvp_mma_kernel,
                         cudaFuncAttributeMaxDynamicSharedMemorySize,
                         SMEM_BYTES);
    int blocks = (N + SB - 1) / SB;
    bvp_mma_kernel<<<blocks, 512, SMEM_BYTES>>>(x, y, z, f, W1, b1, b2, b3,
                                                W4, b4, out, N);
}